// round 1
// baseline (speedup 1.0000x reference)
#include <cuda_runtime.h>

// Problem shape
#define B   4
#define T   8192
#define D   512
#define CH  128          // chunk length (time steps per chunk)
#define NC  (T / CH)     // 64 chunks per sequence
#define TPB 256          // threads per block (channels per block)
#define DGRP (D / TPB)   // 2 channel groups

// Scratch: per-chunk aggregates (a = prod f, b = local scan value) and
// exclusive prefix h at chunk start. Device globals (no allocation allowed).
__device__ float2 g_agg [B * NC * D];
__device__ float  g_pref[B * NC * D];

// Fast-but-accurate activations (__expf: EX2-based, ~2 ulp).
__device__ __forceinline__ float sigm(float x) {
    return 1.0f / (1.0f + __expf(-x));
}
__device__ __forceinline__ float tanh_fast(float x) {
    // tanh(x) = 1 - 2/(e^{2x}+1); saturates correctly for |x| large.
    float e = __expf(2.0f * x);
    return 1.0f - 2.0f / (e + 1.0f);
}

// Pass 1: per-chunk aggregate (a, b). Only needs inp + input-gate columns.
__global__ void __launch_bounds__(TPB)
pass1_chunk_agg(const float* __restrict__ x) {
    const int d = blockIdx.y * TPB + threadIdx.x;
    const int c = blockIdx.x;
    const int b = blockIdx.z;

    const float* base = x + ((size_t)b * T + (size_t)c * CH) * (3 * D);

    float a = 1.0f;
    float h = 0.0f;
#pragma unroll 4
    for (int t = 0; t < CH; ++t) {
        float vi = base[(size_t)t * (3 * D) + d];
        float gi = base[(size_t)t * (3 * D) + D + d];
        float ig = sigm(gi);
        float f  = 1.0f - ig;          // matches reference rounding
        float v  = tanh_fast(vi);
        a = a * f;
        h = f * h + ig * v;
    }
    g_agg[((size_t)b * NC + c) * D + d] = make_float2(a, h);
}

// Pass 2: serial scan over the NC chunk aggregates per (b, d) sequence.
// 2048 sequences -> 2048 threads; trivial cost.
__global__ void __launch_bounds__(TPB)
pass2_seq_scan() {
    const int idx = blockIdx.x * TPB + threadIdx.x;  // 0 .. B*D-1
    if (idx >= B * D) return;
    const int b = idx / D;
    const int d = idx % D;

    float H = 0.0f;
    for (int c = 0; c < NC; ++c) {
        const size_t o = ((size_t)b * NC + c) * D + d;
        g_pref[o] = H;                  // exclusive prefix (h at chunk start)
        float2 ab = g_agg[o];
        H = ab.x * H + ab.y;
    }
}

// Pass 3: recompute each chunk with the correct starting h, write output.
__global__ void __launch_bounds__(TPB)
pass3_emit(const float* __restrict__ x, float* __restrict__ out) {
    const int d = blockIdx.y * TPB + threadIdx.x;
    const int c = blockIdx.x;
    const int b = blockIdx.z;

    const float* base  = x   + ((size_t)b * T + (size_t)c * CH) * (3 * D);
    float*       obase = out + ((size_t)b * T + (size_t)c * CH) * D;

    float h = g_pref[((size_t)b * NC + c) * D + d];

#pragma unroll 4
    for (int t = 0; t < CH; ++t) {
        float vi = base[(size_t)t * (3 * D) + d];
        float gi = base[(size_t)t * (3 * D) + D + d];
        float go = base[(size_t)t * (3 * D) + 2 * D + d];
        float ig = sigm(gi);
        float og = sigm(go);
        float f  = 1.0f - ig;
        float v  = tanh_fast(vi);
        h = f * h + ig * v;
        obase[(size_t)t * D + d] = tanh_fast(h) * og;
    }
}

extern "C" void kernel_launch(void* const* d_in, const int* in_sizes, int n_in,
                              void* d_out, int out_size) {
    const float* x = (const float*)d_in[0];
    float* out = (float*)d_out;

    dim3 grid1(NC, DGRP, B);     // 64 x 2 x 4 = 512 blocks
    pass1_chunk_agg<<<grid1, TPB>>>(x);

    pass2_seq_scan<<<(B * D + TPB - 1) / TPB, TPB>>>();

    dim3 grid3(NC, DGRP, B);
    pass3_emit<<<grid3, TPB>>>(x, out);
}

// round 2
// speedup vs baseline: 1.1799x; 1.1799x over previous
#include <cuda_runtime.h>

// Problem shape
#define B    4
#define T    8192
#define D    512
#define CH   32            // chunk length (time steps per chunk)
#define NC   (T / CH)      // 256 chunks per sequence
#define TPB  128           // threads per block; each thread owns 4 channels
#define VD   (D / 4)       // 128 float4 channel groups

// Scratch (device globals; allocation is forbidden). 2 MiB each -> L2-resident.
__device__ float g_a   [B * NC * D];   // per-chunk product of forget gates
__device__ float g_h   [B * NC * D];   // per-chunk local scan end value
__device__ float g_pref[B * NC * D];   // exclusive prefix h at chunk start

__device__ __forceinline__ float sigm(float x) {
    return 1.0f / (1.0f + __expf(-x));
}
__device__ __forceinline__ float tanh_fast(float x) {
    float e = __expf(2.0f * x);
    return 1.0f - 2.0f / (e + 1.0f);
}

// ---------------------------------------------------------------------------
// Pass 1: per-chunk aggregate (a = prod f, h = local scan). float4 per thread.
// ---------------------------------------------------------------------------
__global__ void __launch_bounds__(TPB)
pass1_chunk_agg(const float* __restrict__ x) {
    const int c = blockIdx.x;          // chunk
    const int b = blockIdx.y;          // batch
    const int d = threadIdx.x * 4;     // channel base

    const float* base = x + ((size_t)b * T + (size_t)c * CH) * (3 * D);

    float a0 = 1.f, a1 = 1.f, a2 = 1.f, a3 = 1.f;
    float h0 = 0.f, h1 = 0.f, h2 = 0.f, h3 = 0.f;

#pragma unroll 4
    for (int t = 0; t < CH; ++t) {
        const float4 vi = *(const float4*)(base + (size_t)t * (3 * D) + d);
        const float4 gi = *(const float4*)(base + (size_t)t * (3 * D) + D + d);

        float i0 = sigm(gi.x), i1 = sigm(gi.y), i2 = sigm(gi.z), i3 = sigm(gi.w);
        float f0 = 1.f - i0,   f1 = 1.f - i1,   f2 = 1.f - i2,   f3 = 1.f - i3;
        float v0 = tanh_fast(vi.x), v1 = tanh_fast(vi.y);
        float v2 = tanh_fast(vi.z), v3 = tanh_fast(vi.w);

        a0 *= f0; a1 *= f1; a2 *= f2; a3 *= f3;
        h0 = f0 * h0 + i0 * v0;
        h1 = f1 * h1 + i1 * v1;
        h2 = f2 * h2 + i2 * v2;
        h3 = f3 * h3 + i3 * v3;
    }

    const size_t o = ((size_t)b * NC + c) * D + d;
    *(float4*)&g_a[o] = make_float4(a0, a1, a2, a3);
    *(float4*)&g_h[o] = make_float4(h0, h1, h2, h3);
}

// ---------------------------------------------------------------------------
// Pass 2: serial scan over NC chunk aggregates per (b, d). 2048 threads.
// Scratch is L2-resident, so the dependent chain is ~L2-latency bound but tiny.
// ---------------------------------------------------------------------------
__global__ void __launch_bounds__(256)
pass2_seq_scan() {
    const int idx = blockIdx.x * 256 + threadIdx.x;  // 0 .. B*D-1
    if (idx >= B * D) return;
    const int b = idx / D;
    const int d = idx % D;

    float H = 0.0f;
#pragma unroll 4
    for (int c = 0; c < NC; ++c) {
        const size_t o = ((size_t)b * NC + c) * D + d;
        g_pref[o] = H;
        H = g_a[o] * H + g_h[o];
    }
}

// ---------------------------------------------------------------------------
// Pass 3: recompute chunk with correct starting h, emit output. float4.
// ---------------------------------------------------------------------------
__global__ void __launch_bounds__(TPB)
pass3_emit(const float* __restrict__ x, float* __restrict__ out) {
    const int c = blockIdx.x;
    const int b = blockIdx.y;
    const int d = threadIdx.x * 4;

    const float* base  = x   + ((size_t)b * T + (size_t)c * CH) * (3 * D);
    float*       obase = out + ((size_t)b * T + (size_t)c * CH) * D;

    const float4 hp = *(const float4*)&g_pref[((size_t)b * NC + c) * D + d];
    float h0 = hp.x, h1 = hp.y, h2 = hp.z, h3 = hp.w;

#pragma unroll 4
    for (int t = 0; t < CH; ++t) {
        const float4 vi = *(const float4*)(base + (size_t)t * (3 * D) + d);
        const float4 gi = *(const float4*)(base + (size_t)t * (3 * D) + D + d);
        const float4 go = *(const float4*)(base + (size_t)t * (3 * D) + 2 * D + d);

        float i0 = sigm(gi.x), i1 = sigm(gi.y), i2 = sigm(gi.z), i3 = sigm(gi.w);
        float f0 = 1.f - i0,   f1 = 1.f - i1,   f2 = 1.f - i2,   f3 = 1.f - i3;
        float v0 = tanh_fast(vi.x), v1 = tanh_fast(vi.y);
        float v2 = tanh_fast(vi.z), v3 = tanh_fast(vi.w);

        h0 = f0 * h0 + i0 * v0;
        h1 = f1 * h1 + i1 * v1;
        h2 = f2 * h2 + i2 * v2;
        h3 = f3 * h3 + i3 * v3;

        float4 o4;
        o4.x = tanh_fast(h0) * sigm(go.x);
        o4.y = tanh_fast(h1) * sigm(go.y);
        o4.z = tanh_fast(h2) * sigm(go.z);
        o4.w = tanh_fast(h3) * sigm(go.w);
        *(float4*)(obase + (size_t)t * D + d) = o4;
    }
}

extern "C" void kernel_launch(void* const* d_in, const int* in_sizes, int n_in,
                              void* d_out, int out_size) {
    const float* x = (const float*)d_in[0];
    float* out = (float*)d_out;

    dim3 grid(NC, B);                       // 256 x 4 = 1024 blocks
    pass1_chunk_agg<<<grid, TPB>>>(x);
    pass2_seq_scan<<<(B * D + 255) / 256, 256>>>();
    pass3_emit<<<grid, TPB>>>(x, out);
}

// round 3
// speedup vs baseline: 1.6001x; 1.3562x over previous
#include <cuda_runtime.h>

// Problem shape
#define B    4
#define HB   2             // batches per half-run (L2 residency trick)
#define T    8192
#define D    512
#define CH   16            // chunk length (time steps per chunk)
#define NC   (T / CH)      // 512 chunks per sequence
#define TPB  128           // threads per block; each thread owns 4 channels

// Scratch (device globals). 4 MiB each.
__device__ float g_a   [B * NC * D];   // per-chunk product of forget gates
__device__ float g_h   [B * NC * D];   // per-chunk local scan end value
__device__ float g_pref[B * NC * D];   // exclusive prefix h at chunk start

__device__ __forceinline__ float sigm(float x) {
    return 1.0f / (1.0f + __expf(-x));
}
__device__ __forceinline__ float tanh_fast(float x) {
    float e = __expf(2.0f * x);
    return 1.0f - 2.0f / (e + 1.0f);
}

// ---------------------------------------------------------------------------
// Pass 1: per-chunk aggregate (a = prod f, h = local scan). float4 per thread.
// ---------------------------------------------------------------------------
__global__ void __launch_bounds__(TPB)
pass1_chunk_agg(const float* __restrict__ x, int b0) {
    const int c = blockIdx.x;
    const int b = b0 + blockIdx.y;
    const int d = threadIdx.x * 4;

    const float* base = x + ((size_t)b * T + (size_t)c * CH) * (3 * D);

    float a0 = 1.f, a1 = 1.f, a2 = 1.f, a3 = 1.f;
    float h0 = 0.f, h1 = 0.f, h2 = 0.f, h3 = 0.f;

#pragma unroll 4
    for (int t = 0; t < CH; ++t) {
        const float4 vi = *(const float4*)(base + (size_t)t * (3 * D) + d);
        const float4 gi = *(const float4*)(base + (size_t)t * (3 * D) + D + d);

        float i0 = sigm(gi.x), i1 = sigm(gi.y), i2 = sigm(gi.z), i3 = sigm(gi.w);
        float f0 = 1.f - i0,   f1 = 1.f - i1,   f2 = 1.f - i2,   f3 = 1.f - i3;
        float v0 = tanh_fast(vi.x), v1 = tanh_fast(vi.y);
        float v2 = tanh_fast(vi.z), v3 = tanh_fast(vi.w);

        a0 *= f0; a1 *= f1; a2 *= f2; a3 *= f3;
        h0 = f0 * h0 + i0 * v0;
        h1 = f1 * h1 + i1 * v1;
        h2 = f2 * h2 + i2 * v2;
        h3 = f3 * h3 + i3 * v3;
    }

    const size_t o = ((size_t)b * NC + c) * D + d;
    *(float4*)&g_a[o] = make_float4(a0, a1, a2, a3);
    *(float4*)&g_h[o] = make_float4(h0, h1, h2, h3);
}

// ---------------------------------------------------------------------------
// Pass 2: one WARP per (b, d) sequence. Shuffle-scan over NC chunk aggregates
// in rounds of 32 with a carried hidden state. Chain: NC/32 rounds only.
// ---------------------------------------------------------------------------
__global__ void __launch_bounds__(256)
pass2_warp_scan(int b0) {
    const int gw   = (blockIdx.x * blockDim.x + threadIdx.x) >> 5;
    const int lane = threadIdx.x & 31;
    if (gw >= HB * D) return;
    const int b = b0 + gw / D;
    const int d = gw % D;

    float H = 0.0f;
    for (int base = 0; base < NC; base += 32) {
        const size_t o = ((size_t)b * NC + base + lane) * D + d;
        float A  = g_a[o];
        float Bv = g_h[o];

        // inclusive scan of (A, Bv) across the warp (earlier lane = earlier time)
#pragma unroll
        for (int off = 1; off < 32; off <<= 1) {
            float Ap = __shfl_up_sync(0xFFFFFFFFu, A,  off);
            float Bp = __shfl_up_sync(0xFFFFFFFFu, Bv, off);
            if (lane >= off) { Bv = A * Bp + Bv; A = A * Ap; }
        }
        // exclusive version
        float Aex = __shfl_up_sync(0xFFFFFFFFu, A,  1);
        float Bex = __shfl_up_sync(0xFFFFFFFFu, Bv, 1);
        if (lane == 0) { Aex = 1.0f; Bex = 0.0f; }

        g_pref[o] = Aex * H + Bex;

        float Al = __shfl_sync(0xFFFFFFFFu, A,  31);
        float Bl = __shfl_sync(0xFFFFFFFFu, Bv, 31);
        H = Al * H + Bl;
    }
}

// ---------------------------------------------------------------------------
// Pass 3: recompute chunk with correct starting h, emit output. float4.
// vi/gi re-reads hit L2 (half-batch working set 64 MiB < 126 MB L2).
// ---------------------------------------------------------------------------
__global__ void __launch_bounds__(TPB)
pass3_emit(const float* __restrict__ x, float* __restrict__ out, int b0) {
    const int c = blockIdx.x;
    const int b = b0 + blockIdx.y;
    const int d = threadIdx.x * 4;

    const float* base  = x   + ((size_t)b * T + (size_t)c * CH) * (3 * D);
    float*       obase = out + ((size_t)b * T + (size_t)c * CH) * D;

    const float4 hp = *(const float4*)&g_pref[((size_t)b * NC + c) * D + d];
    float h0 = hp.x, h1 = hp.y, h2 = hp.z, h3 = hp.w;

#pragma unroll 4
    for (int t = 0; t < CH; ++t) {
        const float4 vi = *(const float4*)(base + (size_t)t * (3 * D) + d);
        const float4 gi = *(const float4*)(base + (size_t)t * (3 * D) + D + d);
        const float4 go = *(const float4*)(base + (size_t)t * (3 * D) + 2 * D + d);

        float i0 = sigm(gi.x), i1 = sigm(gi.y), i2 = sigm(gi.z), i3 = sigm(gi.w);
        float f0 = 1.f - i0,   f1 = 1.f - i1,   f2 = 1.f - i2,   f3 = 1.f - i3;
        float v0 = tanh_fast(vi.x), v1 = tanh_fast(vi.y);
        float v2 = tanh_fast(vi.z), v3 = tanh_fast(vi.w);

        h0 = f0 * h0 + i0 * v0;
        h1 = f1 * h1 + i1 * v1;
        h2 = f2 * h2 + i2 * v2;
        h3 = f3 * h3 + i3 * v3;

        float4 o4;
        o4.x = tanh_fast(h0) * sigm(go.x);
        o4.y = tanh_fast(h1) * sigm(go.y);
        o4.z = tanh_fast(h2) * sigm(go.z);
        o4.w = tanh_fast(h3) * sigm(go.w);
        *(float4*)(obase + (size_t)t * D + d) = o4;
    }
}

extern "C" void kernel_launch(void* const* d_in, const int* in_sizes, int n_in,
                              void* d_out, int out_size) {
    const float* x = (const float*)d_in[0];
    float* out = (float*)d_out;

    const dim3 grid13(NC, HB);                       // 512 x 2 = 1024 blocks
    const int  n_warps = HB * D;                     // 1024 warps for pass2
    const int  p2_blocks = (n_warps * 32 + 255) / 256;

    for (int b0 = 0; b0 < B; b0 += HB) {
        pass1_chunk_agg<<<grid13, TPB>>>(x, b0);
        pass2_warp_scan<<<p2_blocks, 256>>>(b0);
        pass3_emit<<<grid13, TPB>>>(x, out, b0);
    }
}

// round 4
// speedup vs baseline: 1.8265x; 1.1415x over previous
#include <cuda_runtime.h>

// Problem shape
#define B    4
#define HB   2             // batches per half-run (L2 residency for pass3)
#define T    8192
#define D    512
#define CH   8             // chunk length (time steps per chunk)
#define NC   (T / CH)      // 1024 chunks per sequence
#define TPB  128           // threads per block; each thread owns 4 channels

// Scratch (device globals).
// g_ah: per-chunk (a = prod f, h = local end) in TRANSPOSED layout [b][d][c]
//       so pass2 (lane = c) is coalesced. 16 MiB.
// g_pref: exclusive prefix, same [b][d][c] layout. 8 MiB.
__device__ float2 g_ah  [B * D * NC];
__device__ float  g_pref[B * D * NC];

__device__ __forceinline__ float sigm(float x) {
    return __fdividef(1.0f, 1.0f + __expf(-x));
}
__device__ __forceinline__ float tanh_fast(float x) {
    float e = __expf(2.0f * x);
    return 1.0f - __fdividef(2.0f, e + 1.0f);
}

// ---------------------------------------------------------------------------
// Pass 1: per-chunk aggregate (a, h). float4 per thread, 4 channels.
// ---------------------------------------------------------------------------
__global__ void __launch_bounds__(TPB, 12)
pass1_chunk_agg(const float* __restrict__ x, int b0) {
    const int c = blockIdx.x;
    const int b = b0 + blockIdx.y;
    const int d = threadIdx.x * 4;

    const float* base = x + ((size_t)b * T + (size_t)c * CH) * (3 * D);

    float a0 = 1.f, a1 = 1.f, a2 = 1.f, a3 = 1.f;
    float h0 = 0.f, h1 = 0.f, h2 = 0.f, h3 = 0.f;

#pragma unroll
    for (int t = 0; t < CH; ++t) {
        const float4 vi = *(const float4*)(base + (size_t)t * (3 * D) + d);
        const float4 gi = *(const float4*)(base + (size_t)t * (3 * D) + D + d);

        float i0 = sigm(gi.x), i1 = sigm(gi.y), i2 = sigm(gi.z), i3 = sigm(gi.w);
        float f0 = 1.f - i0,   f1 = 1.f - i1,   f2 = 1.f - i2,   f3 = 1.f - i3;
        float v0 = tanh_fast(vi.x), v1 = tanh_fast(vi.y);
        float v2 = tanh_fast(vi.z), v3 = tanh_fast(vi.w);

        a0 *= f0; a1 *= f1; a2 *= f2; a3 *= f3;
        h0 = f0 * h0 + i0 * v0;
        h1 = f1 * h1 + i1 * v1;
        h2 = f2 * h2 + i2 * v2;
        h3 = f3 * h3 + i3 * v3;
    }

    // Transposed scatter: [b][d][c]
    const size_t bd = (size_t)b * D + d;
    g_ah[(bd + 0) * NC + c] = make_float2(a0, h0);
    g_ah[(bd + 1) * NC + c] = make_float2(a1, h1);
    g_ah[(bd + 2) * NC + c] = make_float2(a2, h2);
    g_ah[(bd + 3) * NC + c] = make_float2(a3, h3);
}

// ---------------------------------------------------------------------------
// Pass 2: one WARP per (b, d) sequence. Coalesced loads (lane = chunk index),
// warp shuffle-scan in rounds of 32 with carried hidden state.
// ---------------------------------------------------------------------------
__global__ void __launch_bounds__(256)
pass2_warp_scan(int b0) {
    const int gw   = (blockIdx.x * blockDim.x + threadIdx.x) >> 5;
    const int lane = threadIdx.x & 31;
    if (gw >= HB * D) return;
    const size_t bd = (size_t)(b0 * D) + gw;   // (b, d) flattened

    float H = 0.0f;
    for (int base = 0; base < NC; base += 32) {
        const size_t o = bd * NC + base + lane;
        float2 ah = g_ah[o];
        float A = ah.x, Bv = ah.y;

        // inclusive scan across the warp (earlier lane = earlier chunk)
#pragma unroll
        for (int off = 1; off < 32; off <<= 1) {
            float Ap = __shfl_up_sync(0xFFFFFFFFu, A,  off);
            float Bp = __shfl_up_sync(0xFFFFFFFFu, Bv, off);
            if (lane >= off) { Bv = A * Bp + Bv; A = A * Ap; }
        }
        float Aex = __shfl_up_sync(0xFFFFFFFFu, A,  1);
        float Bex = __shfl_up_sync(0xFFFFFFFFu, Bv, 1);
        if (lane == 0) { Aex = 1.0f; Bex = 0.0f; }

        g_pref[o] = Aex * H + Bex;

        float Al = __shfl_sync(0xFFFFFFFFu, A,  31);
        float Bl = __shfl_sync(0xFFFFFFFFu, Bv, 31);
        H = Al * H + Bl;
    }
}

// ---------------------------------------------------------------------------
// Pass 3: recompute chunk with correct starting h, emit output. float4.
// ---------------------------------------------------------------------------
__global__ void __launch_bounds__(TPB, 12)
pass3_emit(const float* __restrict__ x, float* __restrict__ out, int b0) {
    const int c = blockIdx.x;
    const int b = b0 + blockIdx.y;
    const int d = threadIdx.x * 4;

    const float* base  = x   + ((size_t)b * T + (size_t)c * CH) * (3 * D);
    float*       obase = out + ((size_t)b * T + (size_t)c * CH) * D;

    const size_t bd = (size_t)b * D + d;
    float h0 = g_pref[(bd + 0) * NC + c];
    float h1 = g_pref[(bd + 1) * NC + c];
    float h2 = g_pref[(bd + 2) * NC + c];
    float h3 = g_pref[(bd + 3) * NC + c];

#pragma unroll
    for (int t = 0; t < CH; ++t) {
        const float4 vi = *(const float4*)(base + (size_t)t * (3 * D) + d);
        const float4 gi = *(const float4*)(base + (size_t)t * (3 * D) + D + d);
        const float4 go = *(const float4*)(base + (size_t)t * (3 * D) + 2 * D + d);

        float i0 = sigm(gi.x), i1 = sigm(gi.y), i2 = sigm(gi.z), i3 = sigm(gi.w);
        float f0 = 1.f - i0,   f1 = 1.f - i1,   f2 = 1.f - i2,   f3 = 1.f - i3;
        float v0 = tanh_fast(vi.x), v1 = tanh_fast(vi.y);
        float v2 = tanh_fast(vi.z), v3 = tanh_fast(vi.w);

        h0 = f0 * h0 + i0 * v0;
        h1 = f1 * h1 + i1 * v1;
        h2 = f2 * h2 + i2 * v2;
        h3 = f3 * h3 + i3 * v3;

        float4 o4;
        o4.x = tanh_fast(h0) * sigm(go.x);
        o4.y = tanh_fast(h1) * sigm(go.y);
        o4.z = tanh_fast(h2) * sigm(go.z);
        o4.w = tanh_fast(h3) * sigm(go.w);
        *(float4*)(obase + (size_t)t * D + d) = o4;
    }
}

extern "C" void kernel_launch(void* const* d_in, const int* in_sizes, int n_in,
                              void* d_out, int out_size) {
    const float* x = (const float*)d_in[0];
    float* out = (float*)d_out;

    const dim3 grid13(NC, HB);                    // 1024 x 2 = 2048 blocks/half
    const int  p2_blocks = (HB * D * 32 + 255) / 256;

    for (int b0 = 0; b0 < B; b0 += HB) {
        pass1_chunk_agg<<<grid13, TPB>>>(x, b0);
        pass2_warp_scan<<<p2_blocks, 256>>>(b0);
        pass3_emit<<<grid13, TPB>>>(x, out, b0);
    }
}

// round 5
// speedup vs baseline: 2.7823x; 1.5233x over previous
#include <cuda_runtime.h>

// Problem shape
#define B    4
#define T    8192
#define D    512
#define CH   8                 // time steps per chunk (per block)
#define NC   (T / CH)          // 1024 chunks per sequence
#define TPB  128               // threads; each owns 4 channels
#define LBW  4                 // lookback window

// Flag states
#define FLG_NONE 0
#define FLG_AGG  1
#define FLG_PREF 2

// Scratch (device globals; zero-initialized at module load).
__device__ float2 g_aggv [B * NC * D];       // per-chunk (a = prod f, h = local end)
__device__ float  g_prefh[B * NC * D];       // per-chunk inclusive-prefix h
__device__ int    g_flag [B * NC * TPB];     // per-(chunk, thread-quad) state

__device__ __forceinline__ float tanha(float x) {
    float y;
    asm("tanh.approx.f32 %0, %1;" : "=f"(y) : "f"(x));
    return y;
}
__device__ __forceinline__ float sigm(float x) {
    return fmaf(tanha(0.5f * x), 0.5f, 0.5f);
}

__global__ void __launch_bounds__(TPB, 7)
scan_onepass(const float* __restrict__ x, float* __restrict__ out) {
    __shared__ float sm_f [CH * D];
    __shared__ float sm_iv[CH * D];

    const int c   = blockIdx.x;           // chunk (predecessors have lower bid)
    const int b   = blockIdx.y;           // batch
    const int tid = threadIdx.x;
    const int d   = tid * 4;

    const float* base  = x   + ((size_t)b * T + (size_t)c * CH) * (3 * D);
    float*       obase = out + ((size_t)b * T + (size_t)c * CH) * D;

    // ---------------- Phase 1: local chunk scan, stash f and i*v ----------
    float a0 = 1.f, a1 = 1.f, a2 = 1.f, a3 = 1.f;
    float h0 = 0.f, h1 = 0.f, h2 = 0.f, h3 = 0.f;

#pragma unroll
    for (int t = 0; t < CH; ++t) {
        const float4 vi = *(const float4*)(base + (size_t)t * (3 * D) + d);
        const float4 gi = *(const float4*)(base + (size_t)t * (3 * D) + D + d);

        float i0 = sigm(gi.x), i1 = sigm(gi.y), i2 = sigm(gi.z), i3 = sigm(gi.w);
        float f0 = 1.f - i0,   f1 = 1.f - i1,   f2 = 1.f - i2,   f3 = 1.f - i3;
        float w0 = i0 * tanha(vi.x), w1 = i1 * tanha(vi.y);
        float w2 = i2 * tanha(vi.z), w3 = i3 * tanha(vi.w);

        *(float4*)&sm_f [t * D + d] = make_float4(f0, f1, f2, f3);
        *(float4*)&sm_iv[t * D + d] = make_float4(w0, w1, w2, w3);

        a0 *= f0; a1 *= f1; a2 *= f2; a3 *= f3;
        h0 = fmaf(f0, h0, w0);
        h1 = fmaf(f1, h1, w1);
        h2 = fmaf(f2, h2, w2);
        h3 = fmaf(f3, h3, w3);
    }

    const size_t sidx = ((size_t)b * NC + c) * D + d;   // value base for this chunk
    const int    fbase = (b * NC) * TPB + tid;          // flag index helper

    float He0 = 0.f, He1 = 0.f, He2 = 0.f, He3 = 0.f;  // exclusive prefix h

    if (c == 0) {
        // Inclusive prefix = local; publish PREF directly.
        g_prefh[sidx + 0] = h0;
        g_prefh[sidx + 1] = h1;
        g_prefh[sidx + 2] = h2;
        g_prefh[sidx + 3] = h3;
        __threadfence();
        *(volatile int*)&g_flag[fbase + 0 * TPB] = FLG_PREF;
    } else {
        // Publish aggregate so successors can make progress.
        g_aggv[sidx + 0] = make_float2(a0, h0);
        g_aggv[sidx + 1] = make_float2(a1, h1);
        g_aggv[sidx + 2] = make_float2(a2, h2);
        g_aggv[sidx + 3] = make_float2(a3, h3);
        __threadfence();
        *(volatile int*)&g_flag[fbase + c * TPB] = FLG_AGG;

        // ---------------- Phase 2: decoupled lookback ----------------------
        // Suffix transform S: He = As * H_incl(p_done) + Bs  (per channel)
        float As0 = 1.f, As1 = 1.f, As2 = 1.f, As3 = 1.f;
        float Bs0 = 0.f, Bs1 = 0.f, Bs2 = 0.f, Bs3 = 0.f;

        int p = c - 1;
        bool done = false;
        while (!done) {
            const int w = (p + 1 < LBW) ? (p + 1) : LBW;   // window size

            // Poll flags for p, p-1, ..., p-w+1 until all published.
            int fl[LBW];
            for (;;) {
                bool all = true;
#pragma unroll
                for (int k = 0; k < LBW; ++k) {
                    if (k < w) {
                        fl[k] = *(volatile int*)&g_flag[fbase + (p - k) * TPB];
                        all &= (fl[k] != FLG_NONE);
                    }
                }
                if (all) break;
            }
            __threadfence();

            // Nearest PREF in window (smallest k).
            int kpref = -1;
#pragma unroll
            for (int k = 0; k < LBW; ++k)
                if (k < w && kpref < 0 && fl[k] == FLG_PREF) kpref = k;
            const int kend = (kpref >= 0) ? kpref : (w - 1);

            // Consume near -> far.
            for (int k = 0; k <= kend; ++k) {
                const size_t vb = ((size_t)b * NC + (p - k)) * D + d;
                if (k == kpref) {
                    float p0 = __ldcg(&g_prefh[vb + 0]);
                    float p1 = __ldcg(&g_prefh[vb + 1]);
                    float p2 = __ldcg(&g_prefh[vb + 2]);
                    float p3 = __ldcg(&g_prefh[vb + 3]);
                    He0 = fmaf(As0, p0, Bs0);
                    He1 = fmaf(As1, p1, Bs1);
                    He2 = fmaf(As2, p2, Bs2);
                    He3 = fmaf(As3, p3, Bs3);
                    done = true;
                    break;
                } else {
                    float2 q0 = __ldcg(&g_aggv[vb + 0]);
                    float2 q1 = __ldcg(&g_aggv[vb + 1]);
                    float2 q2 = __ldcg(&g_aggv[vb + 2]);
                    float2 q3 = __ldcg(&g_aggv[vb + 3]);
                    Bs0 = fmaf(As0, q0.y, Bs0); As0 *= q0.x;
                    Bs1 = fmaf(As1, q1.y, Bs1); As1 *= q1.x;
                    Bs2 = fmaf(As2, q2.y, Bs2); As2 *= q2.x;
                    Bs3 = fmaf(As3, q3.y, Bs3); As3 *= q3.x;
                }
            }
            if (!done) {
                p -= w;
                if (p < 0) {  // consumed everything incl. chunk 0 aggregates
                    He0 = Bs0; He1 = Bs1; He2 = Bs2; He3 = Bs3;
                    done = true;
                }
            }
        }

        // Publish inclusive prefix.
        g_prefh[sidx + 0] = fmaf(a0, He0, h0);
        g_prefh[sidx + 1] = fmaf(a1, He1, h1);
        g_prefh[sidx + 2] = fmaf(a2, He2, h2);
        g_prefh[sidx + 3] = fmaf(a3, He3, h3);
        __threadfence();
        *(volatile int*)&g_flag[fbase + c * TPB] = FLG_PREF;
    }

    // ---------------- Phase 3: replay from smem, emit output --------------
    float k0 = He0, k1 = He1, k2 = He2, k3 = He3;
#pragma unroll
    for (int t = 0; t < CH; ++t) {
        const float4 go = *(const float4*)(base + (size_t)t * (3 * D) + 2 * D + d);
        const float4 ff = *(const float4*)&sm_f [t * D + d];
        const float4 iv = *(const float4*)&sm_iv[t * D + d];

        k0 = fmaf(ff.x, k0, iv.x);
        k1 = fmaf(ff.y, k1, iv.y);
        k2 = fmaf(ff.z, k2, iv.z);
        k3 = fmaf(ff.w, k3, iv.w);

        float4 o4;
        o4.x = tanha(k0) * sigm(go.x);
        o4.y = tanha(k1) * sigm(go.y);
        o4.z = tanha(k2) * sigm(go.z);
        o4.w = tanha(k3) * sigm(go.w);
        *(float4*)(obase + (size_t)t * D + d) = o4;
    }
}

extern "C" void kernel_launch(void* const* d_in, const int* in_sizes, int n_in,
                              void* d_out, int out_size) {
    const float* x = (const float*)d_in[0];
    float* out = (float*)d_out;

    dim3 grid(NC, B);   // 1024 x 4 = 4096 blocks; blockIdx.x = chunk (bid-ordered)
    scan_onepass<<<grid, TPB>>>(x, out);
}